// round 10
// baseline (speedup 1.0000x reference)
#include <cuda_runtime.h>
#include <math.h>
#include <cstdint>

// Fixed shape: query_len = key_len = 2048, 8 fp32 channels, TRUNC = 200.
#define QL 2048
#define KL 2048
#define NT 201              // distinct T values 0..200 (T>200 -> T=0 vector)
#define THREADS 256
#define HALF 1024           // CTA = half-row: 1024 px = 32 KB = one bulk copy

__device__ __forceinline__ uint32_t smem_u32(const void* p) {
    uint32_t a;
    asm("{ .reg .u64 t; cvta.to.shared.u64 t, %1; cvt.u32.u64 %0, t; }"
        : "=r"(a) : "l"(p));
    return a;
}

// One CTA = one half-row (32 KB), one bulk copy. Small SMEM footprint
// (~39 KB) -> ~5 CTAs/SM so co-resident fills hide each CTA's TMA drain
// (R9 ran ~2 CTAs/SM, occ 25%, exposing the drain). Exit uses
// wait_group.read (SMEM-read completion only, CUTLASS tma_store_wait
// pattern) instead of the full global-visibility wait.
__global__ __launch_bounds__(THREADS) void fill_half_kernel(
    const float* __restrict__ eta, const float* __restrict__ nu,
    const float* __restrict__ theta, float4* __restrict__ out)
{
    __shared__ __align__(16) float4 buf[HALF * 2];   // 32 KB
    __shared__ __align__(16) float4 lut[2 * NT];     // 6.4 KB

    const int tid = threadIdx.x;
    const int i     = blockIdx.x >> 1;               // row
    const int pbase = (blockIdx.x & 1) * HALF;       // half offset in row

    // ---- LUT build (all fp32; rel_err ~4e-9 verified R2-R9) ----
    if (tid < NT) {
        float lambda = tanhf(eta[0]);
        float gamma  = 1.0f / (1.0f + expf(-nu[0]));
        float th     = theta[0];
        float T      = (float)tid;

        float gT = powf(gamma, T);
        float s, c;  sincosf(T * th, &s, &c);
        float v0 = gT * c;            // ch0, ch1
        float v2 = gT * s;            // ch2, ch3

        float L2d = (tid % 2  == 0) ? T * 0.5f    : 0.0f;
        float L4d = (tid % 4  == 0) ? T * 0.25f   : 0.0f;
        float L8d = (tid % 8  == 0) ? T * 0.125f  : 0.0f;
        float L16 = (tid % 16 == 0) ? T * 0.0625f : 0.0f;

        float v4 = powf(lambda, L2d);                   // ch4
        float v5 = powf(lambda, L4d);                   // ch5
        float s8, c8;   sincosf(L8d * th, &s8, &c8);
        float s16, c16; sincosf(L16 * th, &s16, &c16);
        float v6 = powf(gamma, L8d) * c8;               // ch6
        float v7 = powf(gamma, L16) * s16;              // ch7

        lut[2 * tid]     = make_float4(v0, v0, v2, v2);
        lut[2 * tid + 1] = make_float4(v4, v5, v6, v7);
    }
    __syncthreads();

    const float4 farA = make_float4(1.f, 1.f, 0.f, 0.f);
    const float4 farB = make_float4(1.f, 1.f, 1.f, 0.f);

    // ---- fill 1024 px (4 per thread); far/band branch warp-uniform ----
#pragma unroll
    for (int k = 0; k < HALF / THREADS; k++) {
        const int p = tid + k * THREADS;               // 0..1023 in half
        const int j = pbase + p;
        int T = i - j;  T = (T < 0) ? -T : T;
        float4 a, b;
        if (T <= 200) { a = lut[2 * T]; b = lut[2 * T + 1]; }
        else          { a = farA;       b = farB; }
        buf[2 * p]     = a;
        buf[2 * p + 1] = b;
    }
    __syncthreads();

    // ---- single 32 KB bulk copy; exit after SMEM-read completion ----
    if (tid == 0) {
        asm volatile("fence.proxy.async.shared::cta;" ::: "memory");
        float4* gp = out + ((size_t)i * KL + pbase) * 2;
        asm volatile(
            "cp.async.bulk.global.shared::cta.bulk_group [%0], [%1], %2;"
            :: "l"(gp), "r"(smem_u32(buf)), "r"((uint32_t)(HALF * 32))
            : "memory");
        asm volatile("cp.async.bulk.commit_group;" ::: "memory");
        asm volatile("cp.async.bulk.wait_group.read 0;" ::: "memory");
    }
}

extern "C" void kernel_launch(void* const* d_in, const int* in_sizes, int n_in,
                              void* d_out, int out_size) {
    const float* eta   = (const float*)d_in[0];
    const float* nu    = (const float*)d_in[1];
    const float* theta = (const float*)d_in[2];

    fill_half_kernel<<<QL * 2, THREADS>>>(eta, nu, theta, (float4*)d_out);
}

// round 11
// speedup vs baseline: 1.0013x; 1.0013x over previous
#include <cuda_runtime.h>
#include <math.h>
#include <cstdint>

// Fixed shape: query_len = key_len = 2048, 8 fp32 channels, TRUNC = 200.
#define QL 2048
#define KL 2048
#define NT 201              // distinct T values 0..200 (T>200 -> T=0 vector)
#define THREADS 256
#define CONST_PIX 1024      // const staging buffer: 1024 px = 32 KB
#define BAND_MAX 416        // band <= 401 px

__device__ __forceinline__ uint32_t smem_u32(const void* p) {
    uint32_t a;
    asm("{ .reg .u64 t; cvta.to.shared.u64 t, %1; cvt.u32.u64 %0, t; }"
        : "=r"(a) : "l"(p));
    return a;
}

__device__ __forceinline__ void bulk_s2g(float4* g, uint32_t s, int bytes) {
    asm volatile("cp.async.bulk.global.shared::cta.bulk_group [%0], [%1], %2;"
                 :: "l"(g), "r"(s), "r"(bytes) : "memory");
}

// One CTA = one row. Far region (>=80% of bytes) is TMA-copied from a
// 32 KB constant buffer filled ONCE (R4's trick: cuts STS traffic 4x and
// issue-slot burn, which hit 76% in R10); the far copies are committed
// BEFORE the band fill so the TMA engine streams during it. Exit waits
// only for SMEM-read completion (R10's trick: no global-visibility drain).
__global__ __launch_bounds__(THREADS) void fill_row_kernel(
    const float* __restrict__ eta, const float* __restrict__ nu,
    const float* __restrict__ theta, float4* __restrict__ out)
{
    __shared__ __align__(16) float4 cbuf[CONST_PIX * 2];  // 32 KB, constant
    __shared__ __align__(16) float4 bbuf[BAND_MAX * 2];   // 13 KB, band
    __shared__ __align__(16) float4 lut[2 * NT];          // 6.4 KB

    const int tid = threadIdx.x;
    const int i = blockIdx.x;                  // row index

    // ---- fill constant buffer (far pattern = T-truncated-to-0 vector) ----
    const float4 farA = make_float4(1.f, 1.f, 0.f, 0.f);
    const float4 farB = make_float4(1.f, 1.f, 1.f, 0.f);
#pragma unroll
    for (int k = 0; k < (CONST_PIX * 2) / THREADS; k++) {
        int f = tid + k * THREADS;
        cbuf[f] = (f & 1) ? farB : farA;
    }

    // ---- LUT build (all fp32; rel_err ~4e-9 verified R2-R10) ----
    if (tid < NT) {
        float lambda = tanhf(eta[0]);
        float gamma  = 1.0f / (1.0f + expf(-nu[0]));
        float th     = theta[0];
        float T      = (float)tid;

        float gT = powf(gamma, T);
        float s, c;  sincosf(T * th, &s, &c);
        float v0 = gT * c;            // ch0, ch1
        float v2 = gT * s;            // ch2, ch3

        float L2d = (tid % 2  == 0) ? T * 0.5f    : 0.0f;
        float L4d = (tid % 4  == 0) ? T * 0.25f   : 0.0f;
        float L8d = (tid % 8  == 0) ? T * 0.125f  : 0.0f;
        float L16 = (tid % 16 == 0) ? T * 0.0625f : 0.0f;

        float v4 = powf(lambda, L2d);                   // ch4
        float v5 = powf(lambda, L4d);                   // ch5
        float s8, c8;   sincosf(L8d * th, &s8, &c8);
        float s16, c16; sincosf(L16 * th, &s16, &c16);
        float v6 = powf(gamma, L8d) * c8;               // ch6
        float v7 = powf(gamma, L16) * s16;              // ch7

        lut[2 * tid]     = make_float4(v0, v0, v2, v2);
        lut[2 * tid + 1] = make_float4(v4, v5, v6, v7);
    }
    __syncthreads();

    const int jlo = (i - 200 > 0) ? i - 200 : 0;
    const int jhi = (i + 200 < KL - 1) ? i + 200 : KL - 1;
    const int npix = jhi - jlo + 1;                  // <= 401
    float4* rowp = out + (size_t)i * (2 * KL);

    // ---- tid 0: post + commit all far copies NOW (engine streams while
    //      the band buffer is being filled) ----
    if (tid == 0) {
        asm volatile("fence.proxy.async.shared::cta;" ::: "memory");
        const uint32_t cb = smem_u32(cbuf);

        int rem = jlo, off = 0;                      // left far [0, jlo)
        while (rem > 0) {
            int n = (rem < CONST_PIX) ? rem : CONST_PIX;
            bulk_s2g(rowp + 2 * off, cb, n * 32);
            off += n; rem -= n;
        }
        rem = (KL - 1) - jhi; off = jhi + 1;         // right far (jhi, KL)
        while (rem > 0) {
            int n = (rem < CONST_PIX) ? rem : CONST_PIX;
            bulk_s2g(rowp + 2 * off, cb, n * 32);
            off += n; rem -= n;
        }
        asm volatile("cp.async.bulk.commit_group;" ::: "memory");
    }

    // ---- fill band buffer (<=401 px, T = |i-j| <= 200 by construction) ----
    for (int k = tid; k < npix; k += THREADS) {
        int j = jlo + k;
        int T = i - j;  T = (T < 0) ? -T : T;
        bbuf[2 * k]     = lut[2 * T];
        bbuf[2 * k + 1] = lut[2 * T + 1];
    }
    __syncthreads();

    // ---- band copy; exit after SMEM-read completion only ----
    if (tid == 0) {
        asm volatile("fence.proxy.async.shared::cta;" ::: "memory");
        bulk_s2g(rowp + 2 * jlo, smem_u32(bbuf), npix * 32);
        asm volatile("cp.async.bulk.commit_group;" ::: "memory");
        asm volatile("cp.async.bulk.wait_group.read 0;" ::: "memory");
    }
}

extern "C" void kernel_launch(void* const* d_in, const int* in_sizes, int n_in,
                              void* d_out, int out_size) {
    const float* eta   = (const float*)d_in[0];
    const float* nu    = (const float*)d_in[1];
    const float* theta = (const float*)d_in[2];

    fill_row_kernel<<<QL, THREADS>>>(eta, nu, theta, (float4*)d_out);
}

// round 12
// speedup vs baseline: 1.0299x; 1.0286x over previous
#include <cuda_runtime.h>
#include <math.h>
#include <cstdint>

// Fixed shape: query_len = key_len = 2048, 8 fp32 channels, TRUNC = 200.
#define QL 2048
#define KL 2048
#define NT 201              // distinct T values 0..200 (T>200 -> T=0 vector)
#define THREADS 256
#define HALF 1024           // CTA = half-row (1024 px = 32 KB out)
#define STAGE 512           // copy granule: 512 px = 16 KB

__device__ __forceinline__ uint32_t smem_u32(const void* p) {
    uint32_t a;
    asm("{ .reg .u64 t; cvta.to.shared.u64 t, %1; cvt.u32.u64 %0, t; }"
        : "=r"(a) : "l"(p));
    return a;
}

__device__ __forceinline__ void bulk_s2g(float4* g, uint32_t s, int bytes) {
    asm volatile("cp.async.bulk.global.shared::cta.bulk_group [%0], [%1], %2;"
                 :: "l"(g), "r"(s), "r"(bytes) : "memory");
}

// R10 structure (best kernel so far: half-row CTAs, single-shot copies,
// wait_group.read exit) + two refinements:
//  - pure-far CTAs (~40%) skip the transcendental LUT build and stage only
//    16 KB of constants, shipped as 2 copies;
//  - band CTAs fill/commit in 2 x 16 KB stages so the TMA engine starts
//    half a fill earlier.
__global__ __launch_bounds__(THREADS) void fill_half2_kernel(
    const float* __restrict__ eta, const float* __restrict__ nu,
    const float* __restrict__ theta, float4* __restrict__ out)
{
    __shared__ __align__(16) float4 buf[HALF * 2];   // 32 KB
    __shared__ __align__(16) float4 lut[2 * NT];     // 6.4 KB

    const int tid   = threadIdx.x;
    const int i     = blockIdx.x >> 1;               // row
    const int pbase = (blockIdx.x & 1) * HALF;       // half offset in row

    const float4 farA = make_float4(1.f, 1.f, 0.f, 0.f);
    const float4 farB = make_float4(1.f, 1.f, 1.f, 0.f);
    float4* gp = out + ((size_t)i * KL + pbase) * 2;

    // Does the band |i-j|<=200 intersect this half-row [pbase, pbase+1024)?
    const int blo = (i - 200 > 0) ? i - 200 : 0;
    const int bhi = (i + 200 < KL - 1) ? i + 200 : KL - 1;
    const bool has_band = (bhi >= pbase) && (blo < pbase + HALF);

    if (!has_band) {
        // ---- pure constant half: 16 KB staged once, 2 copies ----
#pragma unroll
        for (int k = 0; k < (STAGE * 2) / THREADS; k++) {
            int f = tid + k * THREADS;
            buf[f] = (f & 1) ? farB : farA;
        }
        __syncthreads();
        if (tid == 0) {
            asm volatile("fence.proxy.async.shared::cta;" ::: "memory");
            const uint32_t sb = smem_u32(buf);
            bulk_s2g(gp,             sb, STAGE * 32);
            bulk_s2g(gp + 2 * STAGE, sb, STAGE * 32);
            asm volatile("cp.async.bulk.commit_group;" ::: "memory");
            asm volatile("cp.async.bulk.wait_group.read 0;" ::: "memory");
        }
        return;
    }

    // ---- band half: LUT build (all fp32; rel_err ~4e-9, R2-R11) ----
    if (tid < NT) {
        float lambda = tanhf(eta[0]);
        float gamma  = 1.0f / (1.0f + expf(-nu[0]));
        float th     = theta[0];
        float T      = (float)tid;

        float gT = powf(gamma, T);
        float s, c;  sincosf(T * th, &s, &c);
        float v0 = gT * c;            // ch0, ch1
        float v2 = gT * s;            // ch2, ch3

        float L2d = (tid % 2  == 0) ? T * 0.5f    : 0.0f;
        float L4d = (tid % 4  == 0) ? T * 0.25f   : 0.0f;
        float L8d = (tid % 8  == 0) ? T * 0.125f  : 0.0f;
        float L16 = (tid % 16 == 0) ? T * 0.0625f : 0.0f;

        float v4 = powf(lambda, L2d);                   // ch4
        float v5 = powf(lambda, L4d);                   // ch5
        float s8, c8;   sincosf(L8d * th, &s8, &c8);
        float s16, c16; sincosf(L16 * th, &s16, &c16);
        float v6 = powf(gamma, L8d) * c8;               // ch6
        float v7 = powf(gamma, L16) * s16;              // ch7

        lut[2 * tid]     = make_float4(v0, v0, v2, v2);
        lut[2 * tid + 1] = make_float4(v4, v5, v6, v7);
    }
    __syncthreads();

    // ---- two 16 KB stages, each committed as soon as it's filled ----
#pragma unroll
    for (int st = 0; st < 2; st++) {
        const int p0 = st * STAGE;
#pragma unroll
        for (int k = 0; k < STAGE / THREADS; k++) {
            const int p = p0 + tid + k * THREADS;      // 0..1023 in half
            const int j = pbase + p;
            int T = i - j;  T = (T < 0) ? -T : T;
            float4 a, b;
            if (T <= 200) { a = lut[2 * T]; b = lut[2 * T + 1]; }
            else          { a = farA;       b = farB; }
            buf[2 * p]     = a;
            buf[2 * p + 1] = b;
        }
        __syncthreads();
        if (tid == 0) {
            asm volatile("fence.proxy.async.shared::cta;" ::: "memory");
            bulk_s2g(gp + 2 * p0, smem_u32(&buf[2 * p0]), STAGE * 32);
            asm volatile("cp.async.bulk.commit_group;" ::: "memory");
        }
    }

    if (tid == 0)
        asm volatile("cp.async.bulk.wait_group.read 0;" ::: "memory");
}

extern "C" void kernel_launch(void* const* d_in, const int* in_sizes, int n_in,
                              void* d_out, int out_size) {
    const float* eta   = (const float*)d_in[0];
    const float* nu    = (const float*)d_in[1];
    const float* theta = (const float*)d_in[2];

    fill_half2_kernel<<<QL * 2, THREADS>>>(eta, nu, theta, (float4*)d_out);
}

// round 13
// speedup vs baseline: 1.1000x; 1.0681x over previous
#include <cuda_runtime.h>
#include <math.h>
#include <cstdint>

// Fixed shape: query_len = key_len = 2048, 8 fp32 channels, TRUNC = 200.
#define QL 2048
#define KL 2048
#define NT 201              // distinct T values 0..200 (T>200 -> T=0 vector)
#define THREADS 256
#define HALF 1024           // CTA = half-row (1024 px = 32 KB out)
#define CPIX 512            // const staging buffer: 512 px = 16 KB
#define BAND_MAX 416        // band within a half-row <= 401 px

__device__ __forceinline__ uint32_t smem_u32(const void* p) {
    uint32_t a;
    asm("{ .reg .u64 t; cvta.to.shared.u64 t, %1; cvt.u32.u64 %0, t; }"
        : "=r"(a) : "l"(p));
    return a;
}

__device__ __forceinline__ void bulk_s2g(float4* g, uint32_t s, int bytes) {
    asm volatile("cp.async.bulk.global.shared::cta.bulk_group [%0], [%1], %2;"
                 :: "l"(g), "r"(s), "r"(bytes) : "memory");
}

// Latency-first schedule: EVERY CTA posts its constant-region copies as
// early as possible (the const buffer needs only 4 trivial STS/thread),
// so the TMA engine starts streaming ~60-100% of the half-row while the
// band CTAs are still running their powf LUT build + band fill. R12 showed
// kernel time tracks prologue-to-first-copy latency, not any pipe%.
__global__ __launch_bounds__(THREADS) void fill_half3_kernel(
    const float* __restrict__ eta, const float* __restrict__ nu,
    const float* __restrict__ theta, float4* __restrict__ out)
{
    __shared__ __align__(16) float4 cbuf[CPIX * 2];      // 16 KB, constant
    __shared__ __align__(16) float4 bbuf[BAND_MAX * 2];  // 13 KB, band
    __shared__ __align__(16) float4 lut[2 * NT];         // 6.4 KB

    const int tid   = threadIdx.x;
    const int i     = blockIdx.x >> 1;              // row
    const int pbase = (blockIdx.x & 1) * HALF;      // half offset in row

    const float4 farA = make_float4(1.f, 1.f, 0.f, 0.f);
    const float4 farB = make_float4(1.f, 1.f, 1.f, 0.f);
    float4* gp = out + ((size_t)i * KL + pbase) * 2;

    // Band |i-j| <= 200 clamped to this half-row [pbase, pbase+HALF).
    int lo = i - 200;  if (lo < pbase) lo = pbase;
    int hi = i + 200;  if (hi > pbase + HALF - 1) hi = pbase + HALF - 1;
    const bool has_band = (lo <= hi);

    // ---- 1) const buffer: 4 STS/thread, then sync ----
#pragma unroll
    for (int k = 0; k < (CPIX * 2) / THREADS; k++) {
        int f = tid + k * THREADS;
        cbuf[f] = (f & 1) ? farB : farA;
    }
    __syncthreads();

    // ---- 2) tid 0: post const-segment copies IMMEDIATELY ----
    if (tid == 0) {
        asm volatile("fence.proxy.async.shared::cta;" ::: "memory");
        const uint32_t cb = smem_u32(cbuf);
        if (!has_band) {
            bulk_s2g(gp,            cb, CPIX * 32);
            bulk_s2g(gp + 2 * CPIX, cb, CPIX * 32);
        } else {
            int rem = lo - pbase, off = 0;            // left const segment
            while (rem > 0) {
                int n = (rem < CPIX) ? rem : CPIX;
                bulk_s2g(gp + 2 * off, cb, n * 32);
                off += n; rem -= n;
            }
            rem = (pbase + HALF - 1) - hi;            // right const segment
            off = hi + 1 - pbase;
            while (rem > 0) {
                int n = (rem < CPIX) ? rem : CPIX;
                bulk_s2g(gp + 2 * off, cb, n * 32);
                off += n; rem -= n;
            }
        }
        asm volatile("cp.async.bulk.commit_group;" ::: "memory");
    }

    if (has_band) {
        // ---- 3) LUT build, overlapped with the streaming const copies ----
        // (all fp32; rel_err ~4e-9 verified R2-R12)
        if (tid < NT) {
            float lambda = tanhf(eta[0]);
            float gamma  = 1.0f / (1.0f + expf(-nu[0]));
            float th     = theta[0];
            float T      = (float)tid;

            float gT = powf(gamma, T);
            float s, c;  sincosf(T * th, &s, &c);
            float v0 = gT * c;            // ch0, ch1
            float v2 = gT * s;            // ch2, ch3

            float L2d = (tid % 2  == 0) ? T * 0.5f    : 0.0f;
            float L4d = (tid % 4  == 0) ? T * 0.25f   : 0.0f;
            float L8d = (tid % 8  == 0) ? T * 0.125f  : 0.0f;
            float L16 = (tid % 16 == 0) ? T * 0.0625f : 0.0f;

            float v4 = powf(lambda, L2d);                   // ch4
            float v5 = powf(lambda, L4d);                   // ch5
            float s8, c8;   sincosf(L8d * th, &s8, &c8);
            float s16, c16; sincosf(L16 * th, &s16, &c16);
            float v6 = powf(gamma, L8d) * c8;               // ch6
            float v7 = powf(gamma, L16) * s16;              // ch7

            lut[2 * tid]     = make_float4(v0, v0, v2, v2);
            lut[2 * tid + 1] = make_float4(v4, v5, v6, v7);
        }
        __syncthreads();

        // ---- 4) band-only fill (<= 401 px; T <= 200 by construction) ----
        const int npix = hi - lo + 1;
        for (int k = tid; k < npix; k += THREADS) {
            int j = lo + k;
            int T = i - j;  T = (T < 0) ? -T : T;
            bbuf[2 * k]     = lut[2 * T];
            bbuf[2 * k + 1] = lut[2 * T + 1];
        }
        __syncthreads();

        // ---- 5) band copy ----
        if (tid == 0) {
            asm volatile("fence.proxy.async.shared::cta;" ::: "memory");
            bulk_s2g(gp + 2 * (lo - pbase), smem_u32(bbuf), npix * 32);
            asm volatile("cp.async.bulk.commit_group;" ::: "memory");
        }
    }

    // Exit after SMEM-read completion only (global visibility is covered
    // by kernel-completion semantics).
    if (tid == 0)
        asm volatile("cp.async.bulk.wait_group.read 0;" ::: "memory");
}

extern "C" void kernel_launch(void* const* d_in, const int* in_sizes, int n_in,
                              void* d_out, int out_size) {
    const float* eta   = (const float*)d_in[0];
    const float* nu    = (const float*)d_in[1];
    const float* theta = (const float*)d_in[2];

    fill_half3_kernel<<<QL * 2, THREADS>>>(eta, nu, theta, (float4*)d_out);
}